// round 15
// baseline (speedup 1.0000x reference)
#include <cuda_runtime.h>

#define H_ 256
#define W_ 256
#define PIX (H_ * W_)
#define MAXB 8
#define TPB 512
#define OCC 3
#define NBLOCKS (OCC * 148)   // 444: proven co-resident via __launch_bounds__(512,3)

__device__ float g_proj[MAXB * PIX];   // zero at load; re-zeroed by each launch
__device__ float g_sum;
__device__ unsigned int g_count;
__device__ unsigned int g_bar1;
__device__ unsigned int g_bar2;

// Predicated atomic add to shared (no BSSY/BSYNC — @p red.shared)
__device__ __forceinline__ void red_shared_pred(int flag, unsigned saddr, float val) {
    asm volatile(
        "{\n\t"
        ".reg .pred p;\n\t"
        "setp.ne.b32 p, %0, 0;\n\t"
        "@p red.shared.add.f32 [%1], %2;\n\t"
        "}" :: "r"(flag), "r"(saddr), "f"(val) : "memory");
}

// Predicated atomic add to global (no BSSY/BSYNC — @p red.global)
__device__ __forceinline__ void red_global_pred(int flag, float* gaddr, float val) {
    asm volatile(
        "{\n\t"
        ".reg .pred p;\n\t"
        "setp.ne.b32 p, %0, 0;\n\t"
        "@p red.global.add.f32 [%1], %2;\n\t"
        "}" :: "r"(flag), "l"(gaddr), "f"(val) : "memory");
}

// Fully branchless point processing.
// Corners -> register accumulators via selects; edges -> smem bins via
// predicated red.shared; interior -> g_proj via predicated red.global.
__device__ __forceinline__ void proc_point(
    float xx, float yy, float zz, float dd,
    float& c00, float& c01, float& c10, float& c11,
    unsigned sb_base, float* __restrict__ gproj_b)
{
    float r256 = __fdividef(256.0f, zz);
    float fu = fmaf(xx, r256, 128.0f);
    float fv = fmaf(yy, r256, 128.0f);
    int u = min(max((int)fu, 0), W_ - 1);
    int v = min(max((int)fv, 0), H_ - 1);
    bool active = dd > 0.5f;
    float av = active ? zz * dd : 0.0f;

    bool u0 = (u == 0), u1 = (u == W_ - 1);
    bool v0 = (v == 0), v1 = (v == H_ - 1);
    bool uc = u0 | u1, vc = v0 | v1;

    // corners: select-add (no atomics, no branches)
    c00 += (u0 & v0) ? av : 0.0f;
    c01 += (u1 & v0) ? av : 0.0f;
    c10 += (u0 & v1) ? av : 0.0f;
    c11 += (u1 & v1) ? av : 0.0f;

    // edge bin: rows [0,512) for v-clamped, cols [512,1024) for u-clamped
    int bbin = vc ? ((v0 ? 0 : 256) + u) : ((u0 ? 512 : 768) + v);
    int edge_f  = (active & (uc ^ vc)) ? 1 : 0;
    int inter_f = (active & !(uc | vc)) ? 1 : 0;

    red_shared_pred(edge_f, sb_base + (unsigned)bbin * 4u, av);
    red_global_pred(inter_f, gproj_b + (v * W_ + u), av);
}

__global__ void __launch_bounds__(TPB, OCC)
fused_kernel(const float* __restrict__ pts,
             const float* __restrict__ dens,
             const float* __restrict__ depth,
             float* __restrict__ out,
             int N, int B, int blocksPerBatch, int nblocks) {
    __shared__ float sb[1024];
    for (int k = threadIdx.x; k < 1024; k += TPB) sb[k] = 0.0f;
    __syncthreads();

    const unsigned sb_base = (unsigned)__cvta_generic_to_shared(sb);

    // ---------------- Phase A: scatter ----------------
    const int b   = blockIdx.x / blocksPerBatch;
    const int blk = blockIdx.x % blocksPerBatch;
    float* __restrict__ gproj_b = &g_proj[b * PIX];
    const float4* __restrict__ pts4  = (const float4*)(pts  + (long)b * N * 3);
    const float4* __restrict__ dens4 = (const float4*)(dens + (long)b * N);

    float c00 = 0.0f, c01 = 0.0f, c10 = 0.0f, c11 = 0.0f;

    const int NQ = N >> 2;                 // quads (N divisible by 4)
    const int stride = blocksPerBatch * TPB;
    for (int q = blk * TPB + threadIdx.x; q < NQ; q += stride) {
        float4 dv = dens4[q];
        float4 p0 = pts4[3 * q + 0];
        float4 p1 = pts4[3 * q + 1];
        float4 p2 = pts4[3 * q + 2];
        proc_point(p0.x, p0.y, p0.z, dv.x, c00, c01, c10, c11, sb_base, gproj_b);
        proc_point(p0.w, p1.x, p1.y, dv.y, c00, c01, c10, c11, sb_base, gproj_b);
        proc_point(p1.z, p1.w, p2.x, dv.z, c00, c01, c10, c11, sb_base, gproj_b);
        proc_point(p2.y, p2.z, p2.w, dv.w, c00, c01, c10, c11, sb_base, gproj_b);
    }
    // scalar tail (empty for N=500000; kept for safety)
    for (int p = 4 * NQ + blk * TPB + threadIdx.x; p < N; p += stride) {
        long i = (long)b * N + p;
        proc_point(pts[3 * i + 0], pts[3 * i + 1], pts[3 * i + 2], dens[i],
                   c00, c01, c10, c11, sb_base, gproj_b);
    }

    // fold corner registers into smem border bins
    #pragma unroll
    for (int o = 16; o > 0; o >>= 1) {
        c00 += __shfl_down_sync(0xffffffffu, c00, o);
        c01 += __shfl_down_sync(0xffffffffu, c01, o);
        c10 += __shfl_down_sync(0xffffffffu, c10, o);
        c11 += __shfl_down_sync(0xffffffffu, c11, o);
    }
    if ((threadIdx.x & 31) == 0) {
        red_shared_pred(c00 != 0.0f, sb_base + 0u * 4u,   c00);
        red_shared_pred(c01 != 0.0f, sb_base + 255u * 4u, c01);
        red_shared_pred(c10 != 0.0f, sb_base + 256u * 4u, c10);
        red_shared_pred(c11 != 0.0f, sb_base + 511u * 4u, c11);
    }
    __syncthreads();

    // flush border bins to global (predicated, branchless)
    for (int k = threadIdx.x; k < 1024; k += TPB) {
        float s = sb[k];
        int u, v;
        if (k < 512) { v = (k < 256) ? 0 : (H_ - 1); u = k & 255; }
        else         { u = (k < 768) ? 0 : (W_ - 1); v = k & 255; }
        red_global_pred(s != 0.0f, gproj_b + (v * W_ + u), s);
    }

    // ---------------- grid barrier ----------------
    __threadfence();
    __syncthreads();
    if (threadIdx.x == 0) {
        atomicAdd(&g_bar1, 1u);
        while (*(volatile unsigned int*)&g_bar1 < (unsigned int)nblocks) {
            __nanosleep(64);
        }
    }
    __syncthreads();
    __threadfence();

    // ---------------- Phase B: reduce + re-zero (float4) ----------------
    const int total4 = (B * PIX) >> 2;     // 131072
    float4* __restrict__ gp4 = (float4*)g_proj;
    const float4* __restrict__ dp4 = (const float4*)depth;
    float s = 0.0f;
    unsigned int c = 0u;
    for (int i = blockIdx.x * TPB + threadIdx.x; i < total4; i += nblocks * TPB) {
        float4 p = gp4[i];
        float4 d = dp4[i];
        gp4[i] = make_float4(0.0f, 0.0f, 0.0f, 0.0f);  // clean for next replay
        float d0 = p.x - d.x, d1 = p.y - d.y, d2 = p.z - d.z, d3 = p.w - d.w;
        s += (p.x > 0.0f) ? d0 * d0 : 0.0f;
        s += (p.y > 0.0f) ? d1 * d1 : 0.0f;
        s += (p.z > 0.0f) ? d2 * d2 : 0.0f;
        s += (p.w > 0.0f) ? d3 * d3 : 0.0f;
        c += (p.x > 0.0f) + (p.y > 0.0f) + (p.z > 0.0f) + (p.w > 0.0f);
    }
    #pragma unroll
    for (int o = 16; o > 0; o >>= 1) {
        s += __shfl_down_sync(0xffffffffu, s, o);
        c += __shfl_down_sync(0xffffffffu, c, o);
    }
    __shared__ float ss[16];
    __shared__ unsigned int scnt[16];
    int lane = threadIdx.x & 31;
    int wid = threadIdx.x >> 5;
    if (lane == 0) { ss[wid] = s; scnt[wid] = c; }
    __syncthreads();
    if (wid == 0) {
        s = (lane < (TPB >> 5)) ? ss[lane] : 0.0f;
        c = (lane < (TPB >> 5)) ? scnt[lane] : 0u;
        #pragma unroll
        for (int o = 8; o > 0; o >>= 1) {
            s += __shfl_down_sync(0xffffffffu, s, o);
            c += __shfl_down_sync(0xffffffffu, c, o);
        }
        if (lane == 0) {
            atomicAdd(&g_sum, s);
            atomicAdd(&g_count, c);
        }
    }

    // ---------------- finalize (last block) ----------------
    __threadfence();
    if (threadIdx.x == 0) {
        unsigned int prev = atomicAdd(&g_bar2, 1u);
        if (prev == (unsigned int)nblocks - 1u) {
            float fs = *(volatile float*)&g_sum;
            unsigned int fc = *(volatile unsigned int*)&g_count;
            if (fc < 1u) fc = 1u;
            out[0] = fs / (float)fc;
            // reset state for next replay (all bar1 spinners have exited:
            // every block incremented bar2 only after passing bar1)
            g_sum = 0.0f;
            g_count = 0u;
            g_bar1 = 0u;
            g_bar2 = 0u;
        }
    }
}

extern "C" void kernel_launch(void* const* d_in, const int* in_sizes, int n_in,
                              void* d_out, int out_size) {
    const float* points = (const float*)d_in[0];   // (B, N, 3)
    const float* dens   = (const float*)d_in[1];   // (B, N, 1)
    const float* depth  = (const float*)d_in[2];   // (B, 1, H, W)
    float* out = (float*)d_out;

    int B = in_sizes[2] / PIX;                     // 8
    int N = in_sizes[0] / (3 * B);                 // 500000

    int blocksPerBatch = NBLOCKS / B;              // 55
    if (blocksPerBatch < 1) blocksPerBatch = 1;
    int nblocks = blocksPerBatch * B;              // 440 for B=8

    fused_kernel<<<nblocks, TPB>>>(points, dens, depth, out,
                                   N, B, blocksPerBatch, nblocks);
}

// round 17
// speedup vs baseline: 1.3992x; 1.3992x over previous
#include <cuda_runtime.h>

#define H_ 256
#define W_ 256
#define PIX (H_ * W_)
#define MAXB 8
#define TPB 512
#define SOCC 4
#define SBPB 74                      // scatter blocks per batch
#define RBLOCKS 256                  // reduce: 256*512 = 131072 float4 = 8*65536 floats

__device__ float g_proj[MAXB * PIX];   // zero at load; re-zeroed by reduce each launch
__device__ float g_sum;
__device__ unsigned int g_count;
__device__ unsigned int g_ticket;

// process one point; corner hits -> register accumulators c00..c11,
// edge hits -> smem border bins, interior -> global atomics
// (branchy version: proven fastest — warps skip untaken arms)
#define PROC(xx, yy, zz, dd) do {                                         \
    if ((dd) > 0.5f) {                                                    \
        float r256 = __fdividef(256.0f, (zz));                            \
        float fu = fmaf((xx), r256, 128.0f);                              \
        float fv = fmaf((yy), r256, 128.0f);                              \
        int u = min(max((int)fu, 0), W_ - 1);                             \
        int v = min(max((int)fv, 0), H_ - 1);                             \
        float val = (zz) * (dd);                                          \
        bool uc = (u == 0) | (u == W_ - 1);                               \
        bool vc = (v == 0) | (v == H_ - 1);                               \
        if (uc & vc) {                                                    \
            if (v == 0) { if (u == 0) c00 += val; else c01 += val; }      \
            else        { if (u == 0) c10 += val; else c11 += val; }      \
        } else if (vc) {                                                  \
            atomicAdd(&sb[(v == 0 ? 0 : 256) + u], val);                  \
        } else if (uc) {                                                  \
            atomicAdd(&sb[(u == 0 ? 512 : 768) + v], val);                \
        } else {                                                          \
            atomicAdd(&g_proj[bpix + v * W_ + u], val);                   \
        }                                                                 \
    }                                                                     \
} while (0)

__global__ void __launch_bounds__(TPB, SOCC)
scatter_kernel(const float* __restrict__ pts,
               const float* __restrict__ dens,
               int N, int blocksPerBatch) {
    __shared__ float sb[1024];
    for (int k = threadIdx.x; k < 1024; k += TPB) sb[k] = 0.0f;
    __syncthreads();

    const int b   = blockIdx.x / blocksPerBatch;
    const int blk = blockIdx.x % blocksPerBatch;
    const int bpix = b * PIX;
    const float4* __restrict__ pts4  = (const float4*)(pts  + (long)b * N * 3);
    const float4* __restrict__ dens4 = (const float4*)(dens + (long)b * N);

    float c00 = 0.0f, c01 = 0.0f, c10 = 0.0f, c11 = 0.0f;

    const int NQ = N >> 2;                 // quads (N divisible by 4)
    const int stride = blocksPerBatch * TPB;
    for (int q = blk * TPB + threadIdx.x; q < NQ; q += stride) {
        float4 dv = dens4[q];
        float4 p0 = pts4[3 * q + 0];
        float4 p1 = pts4[3 * q + 1];
        float4 p2 = pts4[3 * q + 2];
        PROC(p0.x, p0.y, p0.z, dv.x);
        PROC(p0.w, p1.x, p1.y, dv.y);
        PROC(p1.z, p1.w, p2.x, dv.z);
        PROC(p2.y, p2.z, p2.w, dv.w);
    }
    // scalar tail (empty for N=500000; kept for safety)
    for (int p = 4 * NQ + blk * TPB + threadIdx.x; p < N; p += stride) {
        long i = (long)b * N + p;
        float dd = dens[i];
        if (dd > 0.5f) {
            float xx = pts[3 * i + 0], yy = pts[3 * i + 1], zz = pts[3 * i + 2];
            PROC(xx, yy, zz, dd);
        }
    }

    // fold corner registers into smem border bins
    #pragma unroll
    for (int o = 16; o > 0; o >>= 1) {
        c00 += __shfl_down_sync(0xffffffffu, c00, o);
        c01 += __shfl_down_sync(0xffffffffu, c01, o);
        c10 += __shfl_down_sync(0xffffffffu, c10, o);
        c11 += __shfl_down_sync(0xffffffffu, c11, o);
    }
    if ((threadIdx.x & 31) == 0) {
        if (c00 != 0.0f) atomicAdd(&sb[0],   c00);
        if (c01 != 0.0f) atomicAdd(&sb[255], c01);
        if (c10 != 0.0f) atomicAdd(&sb[256], c10);
        if (c11 != 0.0f) atomicAdd(&sb[511], c11);
    }
    __syncthreads();

    // flush border bins to global
    for (int k = threadIdx.x; k < 1024; k += TPB) {
        float s = sb[k];
        if (s != 0.0f) {
            int u, v;
            if (k < 512) { v = (k < 256) ? 0 : (H_ - 1); u = k & 255; }
            else         { u = (k < 768) ? 0 : (W_ - 1); v = k & 255; }
            atomicAdd(&g_proj[bpix + v * W_ + u], s);
        }
    }
}

// One float4 per thread: reduce + re-zero, then last-block ticket finalize
// (no spin over all blocks — deadlock-free at any residency).
__global__ void __launch_bounds__(TPB)
reduce_kernel(const float* __restrict__ depth,
              float* __restrict__ out, int nblocks) {
    const int i = blockIdx.x * TPB + threadIdx.x;
    float4* __restrict__ gp4 = (float4*)g_proj;
    const float4* __restrict__ dp4 = (const float4*)depth;

    float4 p = gp4[i];
    float4 d = dp4[i];
    gp4[i] = make_float4(0.0f, 0.0f, 0.0f, 0.0f);   // clean for next replay
    float d0 = p.x - d.x, d1 = p.y - d.y, d2 = p.z - d.z, d3 = p.w - d.w;
    float s = 0.0f;
    s += (p.x > 0.0f) ? d0 * d0 : 0.0f;
    s += (p.y > 0.0f) ? d1 * d1 : 0.0f;
    s += (p.z > 0.0f) ? d2 * d2 : 0.0f;
    s += (p.w > 0.0f) ? d3 * d3 : 0.0f;
    unsigned int c = (p.x > 0.0f) + (p.y > 0.0f) + (p.z > 0.0f) + (p.w > 0.0f);

    #pragma unroll
    for (int o = 16; o > 0; o >>= 1) {
        s += __shfl_down_sync(0xffffffffu, s, o);
        c += __shfl_down_sync(0xffffffffu, c, o);
    }
    __shared__ float ss[16];
    __shared__ unsigned int scnt[16];
    int lane = threadIdx.x & 31;
    int wid = threadIdx.x >> 5;
    if (lane == 0) { ss[wid] = s; scnt[wid] = c; }
    __syncthreads();
    if (wid == 0) {
        s = (lane < (TPB >> 5)) ? ss[lane] : 0.0f;
        c = (lane < (TPB >> 5)) ? scnt[lane] : 0u;
        #pragma unroll
        for (int o = 8; o > 0; o >>= 1) {
            s += __shfl_down_sync(0xffffffffu, s, o);
            c += __shfl_down_sync(0xffffffffu, c, o);
        }
        if (lane == 0) {
            atomicAdd(&g_sum, s);
            atomicAdd(&g_count, c);
        }
    }

    // last arriving block finalizes (its own sums are already posted)
    __threadfence();
    if (threadIdx.x == 0) {
        unsigned int prev = atomicAdd(&g_ticket, 1u);
        if (prev == (unsigned int)nblocks - 1u) {
            float fs = *(volatile float*)&g_sum;
            unsigned int fc = *(volatile unsigned int*)&g_count;
            if (fc < 1u) fc = 1u;
            out[0] = fs / (float)fc;
            g_sum = 0.0f;
            g_count = 0u;
            g_ticket = 0u;
        }
    }
}

extern "C" void kernel_launch(void* const* d_in, const int* in_sizes, int n_in,
                              void* d_out, int out_size) {
    const float* points = (const float*)d_in[0];   // (B, N, 3)
    const float* dens   = (const float*)d_in[1];   // (B, N, 1)
    const float* depth  = (const float*)d_in[2];   // (B, 1, H, W)
    float* out = (float*)d_out;

    int B = in_sizes[2] / PIX;                     // 8
    int N = in_sizes[0] / (3 * B);                 // 500000

    scatter_kernel<<<B * SBPB, TPB>>>(points, dens, N, SBPB);   // 592 blocks
    reduce_kernel<<<RBLOCKS, TPB>>>(depth, out, RBLOCKS);
}